// round 1
// baseline (speedup 1.0000x reference)
#include <cuda_runtime.h>

#define NROWS 16384
#define DIM   512
#define NCODE 8192

#define TM  64
#define TN  128
#define TKC 16

// output layout (concatenated reference outputs, all f32):
// [0, 8388608)            quantized_st
// 8388608                 loss
// [8388609, +16384)       encoding_indices (as float)
// [8404993, +16384)       min_distances
// 8421377                 loss_commit
#define LOSS_OFF   8388608
#define IDX_OFF    8388609
#define MD_OFF     8404993
#define COMMIT_OFF 8421377

__device__ float g_e2[NCODE];
__device__ float g_x2[NROWS];
__device__ float g_minval[NROWS];
__device__ int   g_minidx[NROWS];

// ---------------------------------------------------------------------------
// Kernel 1: row squared norms for x (16384 rows) and codebook (8192 rows).
// One warp per row.
// ---------------------------------------------------------------------------
__global__ void sq_norms_kernel(const float* __restrict__ x,
                                const float* __restrict__ cb) {
    int warp = (blockIdx.x * blockDim.x + threadIdx.x) >> 5;
    int lane = threadIdx.x & 31;
    const int total = NROWS + NCODE;
    if (warp >= total) return;

    const float4* base;
    if (warp < NROWS) base = (const float4*)(x + (size_t)warp * DIM);
    else              base = (const float4*)(cb + (size_t)(warp - NROWS) * DIM);

    float s = 0.f;
#pragma unroll
    for (int i = 0; i < (DIM / 4) / 32; i++) {
        float4 v = base[lane + i * 32];
        s += v.x * v.x + v.y * v.y + v.z * v.z + v.w * v.w;
    }
#pragma unroll
    for (int o = 16; o > 0; o >>= 1) s += __shfl_down_sync(0xffffffffu, s, o);

    if (lane == 0) {
        if (warp < NROWS) g_x2[warp] = s;
        else              g_e2[warp - NROWS] = s;
    }
}

// ---------------------------------------------------------------------------
// Kernel 2: fused GEMM + argmin.
// Each CTA: TM=64 rows of x, loops over all 8192 codes in TN=128 tiles.
// dist_partial = e2[k] - 2 * dot(x_row, code_k); track running (min, idx).
// 256 threads, per-thread micro-tile 4 rows x 8 cols.
// ---------------------------------------------------------------------------
__global__ __launch_bounds__(256, 2)
void vq_argmin_kernel(const float* __restrict__ x,
                      const float* __restrict__ cb) {
    __shared__ float As[TKC][TM];     // 4 KB, k-major
    __shared__ float Bs[TKC][TN];     // 8 KB, k-major
    __shared__ float red_v[TM][16];   // 4 KB
    __shared__ int   red_i[TM][16];   // 4 KB

    const int tid  = threadIdx.x;
    const int row0 = blockIdx.x * TM;
    const int rowg = tid >> 4;   // 0..15 -> rows rowg*4 .. +3
    const int colg = tid & 15;   // 0..15 -> cols colg*8 .. +7

    // A global-load mapping: thread loads one float4 of row (tid>>2)
    const int ar = tid >> 2;            // 0..63
    const int ak = (tid & 3) << 2;      // 0,4,8,12
    const float* xrow = x + (size_t)(row0 + ar) * DIM + ak;

    float minv[4];
    int   mini[4];
#pragma unroll
    for (int i = 0; i < 4; i++) { minv[i] = 3.4e38f; mini[i] = 0; }

    for (int nt = 0; nt < NCODE; nt += TN) {
        float acc[4][8];
#pragma unroll
        for (int i = 0; i < 4; i++)
#pragma unroll
            for (int j = 0; j < 8; j++) acc[i][j] = 0.f;

        for (int k0 = 0; k0 < DIM; k0 += TKC) {
            __syncthreads();
            // stage A chunk (64 x 16), transposed into k-major smem
            float4 av = *(const float4*)(xrow + k0);
            As[ak + 0][ar] = av.x;
            As[ak + 1][ar] = av.y;
            As[ak + 2][ar] = av.z;
            As[ak + 3][ar] = av.w;
            // stage B chunk (128 x 16): two float4 loads per thread
#pragma unroll
            for (int q = 0; q < 2; q++) {
                int idx = tid + q * 256;
                int c   = idx >> 2;          // 0..127
                int kq  = (idx & 3) << 2;    // 0,4,8,12
                float4 bv = *(const float4*)(cb + (size_t)(nt + c) * DIM + k0 + kq);
                Bs[kq + 0][c] = bv.x;
                Bs[kq + 1][c] = bv.y;
                Bs[kq + 2][c] = bv.z;
                Bs[kq + 3][c] = bv.w;
            }
            __syncthreads();

#pragma unroll
            for (int kk = 0; kk < TKC; kk++) {
                float4 a  = *(const float4*)&As[kk][rowg * 4];
                float4 b0 = *(const float4*)&Bs[kk][colg * 8];
                float4 b1 = *(const float4*)&Bs[kk][colg * 8 + 4];
                float av4[4] = {a.x, a.y, a.z, a.w};
                float bv8[8] = {b0.x, b0.y, b0.z, b0.w, b1.x, b1.y, b1.z, b1.w};
#pragma unroll
                for (int i = 0; i < 4; i++)
#pragma unroll
                    for (int j = 0; j < 8; j++)
                        acc[i][j] = fmaf(av4[i], bv8[j], acc[i][j]);
            }
        }

        // epilogue: dist_partial = e2 - 2*dot ; running argmin
#pragma unroll
        for (int j = 0; j < 8; j++) {
            int col  = nt + colg * 8 + j;
            float e2 = __ldg(&g_e2[col]);
#pragma unroll
            for (int i = 0; i < 4; i++) {
                float d = fmaf(-2.f, acc[i][j], e2);
                if (d < minv[i]) { minv[i] = d; mini[i] = col; }
            }
        }
    }

    // cross-thread reduction: 16 column-groups share each row
#pragma unroll
    for (int i = 0; i < 4; i++) {
        red_v[rowg * 4 + i][colg] = minv[i];
        red_i[rowg * 4 + i][colg] = mini[i];
    }
    __syncthreads();
    if (tid < TM) {
        float bv = red_v[tid][0];
        int   bi = red_i[tid][0];
#pragma unroll
        for (int c = 1; c < 16; c++) {
            float v  = red_v[tid][c];
            int   ix = red_i[tid][c];
            if (v < bv || (v == bv && ix < bi)) { bv = v; bi = ix; }
        }
        g_minval[row0 + tid] = bv;
        g_minidx[row0 + tid] = bi;
    }
}

// ---------------------------------------------------------------------------
// Kernel 3: gather quantized rows + write indices / min_distances.
// One block (128 threads) per row; each thread copies one float4.
// ---------------------------------------------------------------------------
__global__ void vq_finalize_kernel(const float* __restrict__ cb,
                                   float* __restrict__ out) {
    int row = blockIdx.x;
    int t   = threadIdx.x;
    int idx = g_minidx[row];

    const float4* src = (const float4*)(cb + (size_t)idx * DIM);
    float4*       dst = (float4*)(out + (size_t)row * DIM);
    dst[t] = src[t];

    if (t == 0) {
        float md = g_x2[row] + g_minval[row];
        out[IDX_OFF + row] = (float)idx;
        out[MD_OFF + row]  = md;
    }
}

// ---------------------------------------------------------------------------
// Kernel 4: deterministic loss reduction (single block).
// loss_commit = sum(min_distances); loss = 1.25 * loss_commit.
// ---------------------------------------------------------------------------
__global__ void vq_loss_kernel(float* __restrict__ out) {
    __shared__ float s[256];
    int t = threadIdx.x;
    float acc = 0.f;
    for (int i = t; i < NROWS; i += 256) acc += out[MD_OFF + i];
    s[t] = acc;
    __syncthreads();
#pragma unroll
    for (int o = 128; o > 0; o >>= 1) {
        if (t < o) s[t] += s[t + o];
        __syncthreads();
    }
    if (t == 0) {
        out[COMMIT_OFF] = s[0];
        out[LOSS_OFF]   = 1.25f * s[0];
    }
}

// ---------------------------------------------------------------------------
extern "C" void kernel_launch(void* const* d_in, const int* in_sizes, int n_in,
                              void* d_out, int out_size) {
    const float* x  = (const float*)d_in[0];   // [16384, 512]
    const float* cb = (const float*)d_in[1];   // [8192, 512]
    float* out = (float*)d_out;

    // 24576 rows, 8 warps per 256-thread block -> 3072 blocks
    sq_norms_kernel<<<3072, 256>>>(x, cb);
    vq_argmin_kernel<<<NROWS / TM, 256>>>(x, cb);
    vq_finalize_kernel<<<NROWS, 128>>>(cb, out);
    vq_loss_kernel<<<1, 256>>>(out);
}

// round 3
// speedup vs baseline: 5.3412x; 5.3412x over previous
#include <cuda_runtime.h>
#include <cuda_fp16.h>
#include <cstdint>

#define NROWS 16384
#define DIM   512
#define NCODE 8192

#define LOSS_OFF   8388608
#define IDX_OFF    8388609
#define MD_OFF     8404993
#define COMMIT_OFF 8421377

// CTA tile 128(M) x 128(N), warp tile 64x32 (warps 2x4), k-chunk 64
#define TM   128
#define TN   128
#define KC   64
#define NKC  (DIM / KC)     // 8 chunks per n-tile
#define NNT  (NCODE / TN)   // 64 n-tiles
#define TOTAL_CHUNKS (NNT * NKC)  // 512

// dynamic smem: 2 stages x (A_hi 16K | A_lo 16K | B_hi 16K | B_lo 16K)
#define OFF_AHI  0
#define OFF_ALO  16384
#define OFF_BHI  32768
#define OFF_BLO  49152
#define STAGE_SZ 65536
#define SMEM_DYN (2 * STAGE_SZ)

__device__ float g_e2[NCODE];
__device__ float g_x2[NROWS];
__device__ float g_minval[NROWS];
__device__ int   g_minidx[NROWS];
__device__ __half g_xh[NROWS * DIM];
__device__ __half g_xl[NROWS * DIM];
__device__ __half g_ch[NCODE * DIM];
__device__ __half g_cl[NCODE * DIM];

// ---------------------------------------------------------------------------
__device__ __forceinline__ uint32_t smem_u32(const void* p) {
    uint32_t a;
    asm("{ .reg .u64 t; cvta.to.shared.u64 t, %1; cvt.u32.u64 %0, t; }"
        : "=r"(a) : "l"(p));
    return a;
}
__device__ __forceinline__ void cpa16(uint32_t s, const void* g) {
    asm volatile("cp.async.cg.shared.global [%0], [%1], 16;" :: "r"(s), "l"(g));
}
__device__ __forceinline__ void ldsm4(uint32_t* r, uint32_t addr) {
    asm volatile("ldmatrix.sync.aligned.m8n8.x4.shared.b16 {%0,%1,%2,%3}, [%4];"
                 : "=r"(r[0]), "=r"(r[1]), "=r"(r[2]), "=r"(r[3]) : "r"(addr));
}
__device__ __forceinline__ void hmma(float* c, const uint32_t* a,
                                     uint32_t b0, uint32_t b1) {
    asm volatile(
        "mma.sync.aligned.m16n8k16.row.col.f32.f16.f16.f32 "
        "{%0,%1,%2,%3}, {%4,%5,%6,%7}, {%8,%9}, {%0,%1,%2,%3};"
        : "+f"(c[0]), "+f"(c[1]), "+f"(c[2]), "+f"(c[3])
        : "r"(a[0]), "r"(a[1]), "r"(a[2]), "r"(a[3]), "r"(b0), "r"(b1));
}

// ---------------------------------------------------------------------------
// Kernel 0: fp16 hi/lo split of x and codebook
// ---------------------------------------------------------------------------
__global__ void split_kernel(const float* __restrict__ x,
                             const float* __restrict__ cb) {
    const int NX = NROWS * DIM / 4;
    const int NC = NCODE * DIM / 4;
    int i = blockIdx.x * blockDim.x + threadIdx.x;
    const float4* src;
    __half2 *dh, *dl;
    int j;
    if (i < NX)           { src = (const float4*)x;  dh = (__half2*)g_xh; dl = (__half2*)g_xl; j = i; }
    else if (i < NX + NC) { src = (const float4*)cb; dh = (__half2*)g_ch; dl = (__half2*)g_cl; j = i - NX; }
    else return;
    float4 v = src[j];
    __half hx = __float2half_rn(v.x), hy = __float2half_rn(v.y);
    __half hz = __float2half_rn(v.z), hw = __float2half_rn(v.w);
    __half lx = __float2half_rn(v.x - __half2float(hx));
    __half ly = __float2half_rn(v.y - __half2float(hy));
    __half lz = __float2half_rn(v.z - __half2float(hz));
    __half lw = __float2half_rn(v.w - __half2float(hw));
    dh[j * 2 + 0] = __halves2half2(hx, hy);
    dh[j * 2 + 1] = __halves2half2(hz, hw);
    dl[j * 2 + 0] = __halves2half2(lx, ly);
    dl[j * 2 + 1] = __halves2half2(lz, lw);
}

// ---------------------------------------------------------------------------
// Kernel 1: row squared norms (one warp per row) on fp32 originals
// ---------------------------------------------------------------------------
__global__ void sq_norms_kernel(const float* __restrict__ x,
                                const float* __restrict__ cb) {
    int warp = (blockIdx.x * blockDim.x + threadIdx.x) >> 5;
    int lane = threadIdx.x & 31;
    if (warp >= NROWS + NCODE) return;
    const float4* base = (warp < NROWS)
        ? (const float4*)(x + (size_t)warp * DIM)
        : (const float4*)(cb + (size_t)(warp - NROWS) * DIM);
    float s = 0.f;
#pragma unroll
    for (int i = 0; i < (DIM / 4) / 32; i++) {
        float4 v = base[lane + i * 32];
        s += v.x * v.x + v.y * v.y + v.z * v.z + v.w * v.w;
    }
#pragma unroll
    for (int o = 16; o > 0; o >>= 1) s += __shfl_down_sync(0xffffffffu, s, o);
    if (lane == 0) {
        if (warp < NROWS) g_x2[warp] = s;
        else              g_e2[warp - NROWS] = s;
    }
}

// ---------------------------------------------------------------------------
// Kernel 2: fp16x3-split mma.sync GEMM + fused argmin
// ---------------------------------------------------------------------------
__global__ __launch_bounds__(256, 1)
void vq_mma_kernel() {
    extern __shared__ __align__(1024) char smem[];
    __shared__ float e2s[TN];
    __shared__ float redv[TM][4];
    __shared__ int   redi[TM][4];

    const uint32_t sb = smem_u32(smem);
    const int tid    = threadIdx.x;
    const int wid    = tid >> 5;
    const int lane   = tid & 31;
    const int warp_m = wid >> 2;     // 0..1
    const int warp_n = wid & 3;      // 0..3
    const int row0   = blockIdx.x * TM;

    // cp.async source/dest mapping for this thread (4 x 16B per array per chunk)
    // id = tid + i*256 -> r = id>>3 (0..127), c = id&7 (16B column)
    // swizzled smem offset: r*128 + ((c ^ (r&7))<<4)
    // ldmatrix lane addressing
    const int rA = (lane & 7) + ((lane >> 3) & 1) * 8;
    const int cA = lane >> 4;
    const int rB = (lane & 7) + (lane >> 4) * 8;
    const int cB = (lane >> 3) & 1;
    const int swl = lane & 7;
    const uint32_t aRow = (uint32_t)(warp_m * 64 + rA) * 128;
    const uint32_t bRow = (uint32_t)(warp_n * 32 + rB) * 128;

    float minv = 3.4e38f;
    int   mini = 0;

    // chunk loader: cc = nt*8 + kc
    auto load_chunk = [&](int cc) {
        const int nt = cc >> 3;
        const int kc = cc & 7;
        const uint32_t st = sb + (uint32_t)(cc & 1) * STAGE_SZ;
#pragma unroll
        for (int i = 0; i < 4; i++) {
            int id = tid + i * 256;
            int r = id >> 3, c = id & 7;
            uint32_t so = (uint32_t)(r * 128 + ((c ^ (r & 7)) << 4));
            size_t ga = (size_t)(row0 + r) * DIM + kc * KC + c * 8;
            size_t gb = (size_t)(nt * TN + r) * DIM + kc * KC + c * 8;
            cpa16(st + OFF_AHI + so, g_xh + ga);
            cpa16(st + OFF_ALO + so, g_xl + ga);
            cpa16(st + OFF_BHI + so, g_ch + gb);
            cpa16(st + OFF_BLO + so, g_cl + gb);
        }
        asm volatile("cp.async.commit_group;");
    };

    float acc[4][4][4];
#pragma unroll
    for (int a = 0; a < 4; a++)
#pragma unroll
        for (int b = 0; b < 4; b++)
#pragma unroll
            for (int c = 0; c < 4; c++) acc[a][b][c] = 0.f;

    load_chunk(0);

    for (int nt = 0; nt < NNT; nt++) {
#pragma unroll 1
        for (int kc = 0; kc < NKC; kc++) {
            const int cc = nt * NKC + kc;
            if (cc + 1 < TOTAL_CHUNKS) {
                load_chunk(cc + 1);
                asm volatile("cp.async.wait_group 1;");
            } else {
                asm volatile("cp.async.wait_group 0;");
            }
            __syncthreads();

            const uint32_t st = sb + (uint32_t)(cc & 1) * STAGE_SZ;
#pragma unroll
            for (int ks = 0; ks < 4; ks++) {
                uint32_t ah[4][4], al[4][4], bh[2][4], bl[2][4];
                const uint32_t swA = (uint32_t)(((ks * 2 + cA) ^ swl) << 4);
                const uint32_t swB = (uint32_t)(((ks * 2 + cB) ^ swl) << 4);
#pragma unroll
                for (int mi = 0; mi < 4; mi++) {
                    uint32_t base = st + aRow + mi * 2048 + swA;
                    ldsm4(ah[mi], base + OFF_AHI);
                    ldsm4(al[mi], base + OFF_ALO);
                }
#pragma unroll
                for (int np = 0; np < 2; np++) {
                    uint32_t base = st + bRow + np * 2048 + swB;
                    ldsm4(bh[np], base + OFF_BHI);
                    ldsm4(bl[np], base + OFF_BLO);
                }
#pragma unroll
                for (int mi = 0; mi < 4; mi++) {
#pragma unroll
                    for (int nj = 0; nj < 4; nj++) {
                        const int np = nj >> 1, q = (nj & 1) * 2;
                        hmma(acc[mi][nj], ah[mi], bh[np][q], bh[np][q + 1]);
                        hmma(acc[mi][nj], ah[mi], bl[np][q], bl[np][q + 1]);
                        hmma(acc[mi][nj], al[mi], bh[np][q], bh[np][q + 1]);
                    }
                }
            }
            __syncthreads();
        }

        // ---- epilogue: dist = e2 - 2*dot, fused argmin over this n-tile ----
        if (tid < TN) e2s[tid] = g_e2[nt * TN + tid];
        __syncthreads();

        const int g = lane >> 2, t = lane & 3;
#pragma unroll
        for (int mi = 0; mi < 4; mi++) {
#pragma unroll
            for (int p = 0; p < 2; p++) {
                float mv = 3.4e38f; int mc = 0;
#pragma unroll
                for (int nj = 0; nj < 4; nj++) {
                    int col0 = warp_n * 32 + nj * 8 + 2 * t;
                    float d0 = fmaf(-2.f, acc[mi][nj][p * 2 + 0], e2s[col0]);
                    float d1 = fmaf(-2.f, acc[mi][nj][p * 2 + 1], e2s[col0 + 1]);
                    if (d0 < mv) { mv = d0; mc = col0; }
                    if (d1 < mv) { mv = d1; mc = col0 + 1; }
                    acc[mi][nj][p * 2 + 0] = 0.f;
                    acc[mi][nj][p * 2 + 1] = 0.f;
                }
#pragma unroll
                for (int off = 1; off <= 2; off <<= 1) {
                    float ov = __shfl_xor_sync(0xffffffffu, mv, off);
                    int   oc = __shfl_xor_sync(0xffffffffu, mc, off);
                    if (ov < mv || (ov == mv && oc < mc)) { mv = ov; mc = oc; }
                }
                if (t == 0) {
                    int rl = warp_m * 64 + mi * 16 + p * 8 + g;
                    redv[rl][warp_n] = mv;
                    redi[rl][warp_n] = nt * TN + mc;
                }
            }
        }
        __syncthreads();

        if (tid < TM) {
#pragma unroll
            for (int w = 0; w < 4; w++) {
                float v = redv[tid][w];
                int   ix = redi[tid][w];
                if (v < minv || (v == minv && ix < mini)) { minv = v; mini = ix; }
            }
        }
        __syncthreads();
    }

    if (tid < TM) {
        g_minval[row0 + tid] = minv;
        g_minidx[row0 + tid] = mini;
    }
}

// ---------------------------------------------------------------------------
// Kernel 3: gather quantized rows + indices / min_distances
// ---------------------------------------------------------------------------
__global__ void vq_finalize_kernel(const float* __restrict__ cb,
                                   float* __restrict__ out) {
    int row = blockIdx.x;
    int t   = threadIdx.x;
    int idx = g_minidx[row];
    const float4* src = (const float4*)(cb + (size_t)idx * DIM);
    float4*       dst = (float4*)(out + (size_t)row * DIM);
    dst[t] = src[t];
    if (t == 0) {
        out[IDX_OFF + row] = (float)idx;
        out[MD_OFF + row]  = g_x2[row] + g_minval[row];
    }
}

// ---------------------------------------------------------------------------
// Kernel 4: deterministic loss reduction
// ---------------------------------------------------------------------------
__global__ void vq_loss_kernel(float* __restrict__ out) {
    __shared__ float s[256];
    int t = threadIdx.x;
    float acc = 0.f;
    for (int i = t; i < NROWS; i += 256) acc += out[MD_OFF + i];
    s[t] = acc;
    __syncthreads();
#pragma unroll
    for (int o = 128; o > 0; o >>= 1) {
        if (t < o) s[t] += s[t + o];
        __syncthreads();
    }
    if (t == 0) {
        out[COMMIT_OFF] = s[0];
        out[LOSS_OFF]   = 1.25f * s[0];
    }
}

// ---------------------------------------------------------------------------
extern "C" void kernel_launch(void* const* d_in, const int* in_sizes, int n_in,
                              void* d_out, int out_size) {
    const float* x  = (const float*)d_in[0];   // [16384, 512]
    const float* cb = (const float*)d_in[1];   // [8192, 512]
    float* out = (float*)d_out;

    cudaFuncSetAttribute(vq_mma_kernel,
                         cudaFuncAttributeMaxDynamicSharedMemorySize, SMEM_DYN);

    split_kernel<<<(NROWS + NCODE) * (DIM / 4) / 256, 256>>>(x, cb);
    sq_norms_kernel<<<(NROWS + NCODE) / 8, 256>>>(x, cb);
    vq_mma_kernel<<<NROWS / TM, 256, SMEM_DYN>>>();
    vq_finalize_kernel<<<NROWS, 128>>>(cb, out);
    vq_loss_kernel<<<1, 256>>>(out);
}

// round 4
// speedup vs baseline: 7.6582x; 1.4338x over previous
#include <cuda_runtime.h>
#include <cuda_fp16.h>
#include <cstdint>

#define NROWS 16384
#define DIM   512
#define NCODE 8192

#define LOSS_OFF   8388608
#define IDX_OFF    8388609
#define MD_OFF     8404993
#define COMMIT_OFF 8421377

// CTA tile 128x128, 4 warps (2x2), warp tile 64x64, k-chunk 64
#define TM   128
#define TN   128
#define KC   64
#define NKC  (DIM / KC)            // 8
#define NNT  (NCODE / TN)          // 64
#define TOTAL_CHUNKS (NNT * NKC)   // 512

// dynamic smem: 4 stages x (A 16K | B 16K) + dist[128][130] + e2s[128]
#define OFF_A    0
#define OFF_B    16384
#define STAGE_SZ 32768
#define DIST_OFF (4 * STAGE_SZ)            // 131072
#define E2_OFF   (DIST_OFF + 128*130*4)    // 197632
#define SMEM_DYN (E2_OFF + 512)            // 198144

__device__ float  g_e2[NCODE];
__device__ __half g_xh[NROWS * DIM];
__device__ __half g_ch[NCODE * DIM];
__device__ int    g_cand[NROWS * 4];

// ---------------------------------------------------------------------------
__device__ __forceinline__ uint32_t smem_u32(const void* p) {
    uint32_t a;
    asm("{ .reg .u64 t; cvta.to.shared.u64 t, %1; cvt.u32.u64 %0, t; }"
        : "=r"(a) : "l"(p));
    return a;
}
__device__ __forceinline__ void cpa16(uint32_t s, const void* g) {
    asm volatile("cp.async.cg.shared.global [%0], [%1], 16;" :: "r"(s), "l"(g));
}
__device__ __forceinline__ void ldsm4(uint32_t* r, uint32_t addr) {
    asm volatile("ldmatrix.sync.aligned.m8n8.x4.shared.b16 {%0,%1,%2,%3}, [%4];"
                 : "=r"(r[0]), "=r"(r[1]), "=r"(r[2]), "=r"(r[3]) : "r"(addr));
}
__device__ __forceinline__ void hmma(float* c, const uint32_t* a,
                                     uint32_t b0, uint32_t b1) {
    asm volatile(
        "mma.sync.aligned.m16n8k16.row.col.f32.f16.f16.f32 "
        "{%0,%1,%2,%3}, {%4,%5,%6,%7}, {%8,%9}, {%0,%1,%2,%3};"
        : "+f"(c[0]), "+f"(c[1]), "+f"(c[2]), "+f"(c[3])
        : "r"(a[0]), "r"(a[1]), "r"(a[2]), "r"(a[3]), "r"(b0), "r"(b1));
}

// ---------------------------------------------------------------------------
// Kernel 0: fp16 hi conversion of x and codebook
// ---------------------------------------------------------------------------
__global__ void split_kernel(const float* __restrict__ x,
                             const float* __restrict__ cb) {
    const int NX = NROWS * DIM / 4;
    const int NC = NCODE * DIM / 4;
    int i = blockIdx.x * blockDim.x + threadIdx.x;
    const float4* src;
    __half2* dh;
    int j;
    if (i < NX)           { src = (const float4*)x;  dh = (__half2*)g_xh; j = i; }
    else if (i < NX + NC) { src = (const float4*)cb; dh = (__half2*)g_ch; j = i - NX; }
    else return;
    float4 v = src[j];
    dh[j * 2 + 0] = __halves2half2(__float2half_rn(v.x), __float2half_rn(v.y));
    dh[j * 2 + 1] = __halves2half2(__float2half_rn(v.z), __float2half_rn(v.w));
}

// ---------------------------------------------------------------------------
// Kernel 1: codebook squared norms (one warp per row, fp32)
// ---------------------------------------------------------------------------
__global__ void sq_norms_kernel(const float* __restrict__ cb) {
    int warp = (blockIdx.x * blockDim.x + threadIdx.x) >> 5;
    int lane = threadIdx.x & 31;
    if (warp >= NCODE) return;
    const float4* base = (const float4*)(cb + (size_t)warp * DIM);
    float s = 0.f;
#pragma unroll
    for (int i = 0; i < 4; i++) {
        float4 v = base[lane + i * 32];
        s += v.x * v.x + v.y * v.y + v.z * v.z + v.w * v.w;
    }
#pragma unroll
    for (int o = 16; o > 0; o >>= 1) s += __shfl_down_sync(0xffffffffu, s, o);
    if (lane == 0) g_e2[warp] = s;
}

// ---------------------------------------------------------------------------
// Kernel 2: fp16 hi GEMM + per-row top-4 approximate argmin candidates
// ---------------------------------------------------------------------------
__global__ __launch_bounds__(128, 1)
void vq_mma_kernel() {
    extern __shared__ __align__(1024) char smem[];
    const uint32_t sb = smem_u32(smem);
    float* dsm = (float*)(smem + DIST_OFF);
    float* e2s = (float*)(smem + E2_OFF);

    const int tid    = threadIdx.x;
    const int wid    = tid >> 5;
    const int lane   = tid & 31;
    const int warp_m = wid >> 1;   // 0..1
    const int warp_n = wid & 1;    // 0..1
    const int row0   = blockIdx.x * TM;

    // ldmatrix lane addressing (same scheme as validated round-3 kernel)
    const int rA  = (lane & 7) + ((lane >> 3) & 1) * 8;
    const int cA  = lane >> 4;
    const int rB  = (lane & 7) + (lane >> 4) * 8;
    const int cB  = (lane >> 3) & 1;
    const int swl = lane & 7;
    const uint32_t aRow = (uint32_t)(warp_m * 64 + rA) * 128;
    const uint32_t bRow = (uint32_t)(warp_n * 64 + rB) * 128;

    // chunk loader: cc = nt*8 + kc ; stage = cc & 3
    auto load_chunk = [&](int cc) {
        const int nt = cc >> 3;
        const int kc = cc & 7;
        const uint32_t st = sb + (uint32_t)(cc & 3) * STAGE_SZ;
#pragma unroll
        for (int i = 0; i < 8; i++) {
            int id = tid + i * 128;
            int r = id >> 3, c = id & 7;
            uint32_t so = (uint32_t)(r * 128 + ((c ^ (r & 7)) << 4));
            size_t ga = (size_t)(row0 + r) * DIM + kc * KC + c * 8;
            size_t gb = (size_t)(nt * TN + r) * DIM + kc * KC + c * 8;
            cpa16(st + OFF_A + so, g_xh + ga);
            cpa16(st + OFF_B + so, g_ch + gb);
        }
    };

    float acc[4][8][4];
#pragma unroll
    for (int a = 0; a < 4; a++)
#pragma unroll
        for (int b = 0; b < 8; b++)
#pragma unroll
            for (int c = 0; c < 4; c++) acc[a][b][c] = 0.f;

    // per-row top-4 (ascending)
    float tv0 = 3.4e38f, tv1 = 3.4e38f, tv2 = 3.4e38f, tv3 = 3.4e38f;
    int   ti0 = 0, ti1 = 0, ti2 = 0, ti3 = 0;

    // prologue: 3 chunks in flight
    load_chunk(0); asm volatile("cp.async.commit_group;");
    load_chunk(1); asm volatile("cp.async.commit_group;");
    load_chunk(2); asm volatile("cp.async.commit_group;");

    const int g  = lane >> 2;
    const int t4 = lane & 3;

#pragma unroll 1
    for (int cc = 0; cc < TOTAL_CHUNKS; cc++) {
        if (cc + 3 < TOTAL_CHUNKS) load_chunk(cc + 3);
        asm volatile("cp.async.commit_group;");   // empty group at tail is fine
        asm volatile("cp.async.wait_group 3;");
        __syncthreads();

        const uint32_t st = sb + (uint32_t)(cc & 3) * STAGE_SZ;
#pragma unroll
        for (int ks = 0; ks < 4; ks++) {
            uint32_t ah[4][4], bh[4][4];
            const uint32_t swA = (uint32_t)(((ks * 2 + cA) ^ swl) << 4);
            const uint32_t swB = (uint32_t)(((ks * 2 + cB) ^ swl) << 4);
#pragma unroll
            for (int mi = 0; mi < 4; mi++)
                ldsm4(ah[mi], st + OFF_A + aRow + mi * 2048 + swA);
#pragma unroll
            for (int np = 0; np < 4; np++)
                ldsm4(bh[np], st + OFF_B + bRow + np * 2048 + swB);
#pragma unroll
            for (int mi = 0; mi < 4; mi++)
#pragma unroll
                for (int nj = 0; nj < 8; nj++)
                    hmma(acc[mi][nj], ah[mi],
                         bh[nj >> 1][(nj & 1) * 2], bh[nj >> 1][(nj & 1) * 2 + 1]);
        }

        if ((cc & 7) == 7) {
            const int nt = cc >> 3;
            // store raw dots into padded dist smem; reset accumulators
#pragma unroll
            for (int mi = 0; mi < 4; mi++)
#pragma unroll
                for (int nj = 0; nj < 8; nj++)
#pragma unroll
                    for (int p = 0; p < 2; p++) {
                        int row = warp_m * 64 + mi * 16 + p * 8 + g;
                        int col = warp_n * 64 + nj * 8 + 2 * t4;
                        *(float2*)&dsm[row * 130 + col] =
                            make_float2(acc[mi][nj][p * 2], acc[mi][nj][p * 2 + 1]);
                        acc[mi][nj][p * 2] = 0.f;
                        acc[mi][nj][p * 2 + 1] = 0.f;
                    }
            e2s[tid] = g_e2[nt * TN + tid];
            __syncthreads();

            // each thread scans its own row, maintaining top-4
            const float* drow = &dsm[tid * 130];
#pragma unroll 4
            for (int j = 0; j < TN; j++) {
                float d = fmaf(-2.f, drow[j], e2s[j]);
                if (d < tv3) {
                    int gi = nt * TN + j;
                    if (d < tv1) {
                        if (d < tv0) {
                            tv3=tv2; ti3=ti2; tv2=tv1; ti2=ti1; tv1=tv0; ti1=ti0;
                            tv0=d; ti0=gi;
                        } else {
                            tv3=tv2; ti3=ti2; tv2=tv1; ti2=ti1; tv1=d; ti1=gi;
                        }
                    } else {
                        if (d < tv2) { tv3=tv2; ti3=ti2; tv2=d; ti2=gi; }
                        else         { tv3=d; ti3=gi; }
                    }
                }
            }
            // no sync needed: next tile's dist writes are separated by 8 chunk barriers
        }
    }

    int row = row0 + tid;
    g_cand[row * 4 + 0] = ti0;
    g_cand[row * 4 + 1] = ti1;
    g_cand[row * 4 + 2] = ti2;
    g_cand[row * 4 + 3] = ti3;
}

// ---------------------------------------------------------------------------
// Kernel 3: exact fp32 refine of 4 candidates + gather + outputs
// ---------------------------------------------------------------------------
__global__ __launch_bounds__(128)
void vq_refine_kernel(const float* __restrict__ x,
                      const float* __restrict__ cb,
                      float* __restrict__ out) {
    __shared__ float sv[4];
    __shared__ int   si[4];
    __shared__ int   swin;

    const int row  = blockIdx.x;
    const int tid  = threadIdx.x;
    const int wid  = tid >> 5;
    const int lane = tid & 31;

    int cand = g_cand[row * 4 + wid];
    const float4* x4 = (const float4*)(x  + (size_t)row  * DIM);
    const float4* e4 = (const float4*)(cb + (size_t)cand * DIM);
    float s = 0.f;
#pragma unroll
    for (int i = 0; i < 4; i++) {
        float4 xv = x4[lane + i * 32];
        float4 ev = e4[lane + i * 32];
        float dx = xv.x - ev.x, dy = xv.y - ev.y;
        float dz = xv.z - ev.z, dw = xv.w - ev.w;
        s += dx * dx + dy * dy + dz * dz + dw * dw;
    }
#pragma unroll
    for (int o = 16; o > 0; o >>= 1) s += __shfl_down_sync(0xffffffffu, s, o);
    if (lane == 0) { sv[wid] = s; si[wid] = cand; }
    __syncthreads();

    if (tid == 0) {
        float bv = sv[0]; int bi = si[0];
#pragma unroll
        for (int k = 1; k < 4; k++) {
            float v = sv[k]; int ix = si[k];
            if (v < bv || (v == bv && ix < bi)) { bv = v; bi = ix; }
        }
        out[IDX_OFF + row] = (float)bi;
        out[MD_OFF + row]  = bv;
        swin = bi;
    }
    __syncthreads();

    int win = swin;
    const float4* src = (const float4*)(cb + (size_t)win * DIM);
    float4*       dst = (float4*)(out + (size_t)row * DIM);
    dst[tid] = src[tid];
}

// ---------------------------------------------------------------------------
// Kernel 4: deterministic loss reduction
// ---------------------------------------------------------------------------
__global__ void vq_loss_kernel(float* __restrict__ out) {
    __shared__ float s[256];
    int t = threadIdx.x;
    float acc = 0.f;
    for (int i = t; i < NROWS; i += 256) acc += out[MD_OFF + i];
    s[t] = acc;
    __syncthreads();
#pragma unroll
    for (int o = 128; o > 0; o >>= 1) {
        if (t < o) s[t] += s[t + o];
        __syncthreads();
    }
    if (t == 0) {
        out[COMMIT_OFF] = s[0];
        out[LOSS_OFF]   = 1.25f * s[0];
    }
}

// ---------------------------------------------------------------------------
extern "C" void kernel_launch(void* const* d_in, const int* in_sizes, int n_in,
                              void* d_out, int out_size) {
    const float* x  = (const float*)d_in[0];   // [16384, 512]
    const float* cb = (const float*)d_in[1];   // [8192, 512]
    float* out = (float*)d_out;

    cudaFuncSetAttribute(vq_mma_kernel,
                         cudaFuncAttributeMaxDynamicSharedMemorySize, SMEM_DYN);

    split_kernel<<<(NROWS + NCODE) * (DIM / 4) / 256, 256>>>(x, cb);
    sq_norms_kernel<<<NCODE / 8, 256>>>(cb);
    vq_mma_kernel<<<NROWS / TM, 128, SMEM_DYN>>>();
    vq_refine_kernel<<<NROWS, 128>>>(x, cb, out);
    vq_loss_kernel<<<1, 256>>>(out);
}

// round 5
// speedup vs baseline: 12.2444x; 1.5989x over previous
#include <cuda_runtime.h>
#include <cuda_fp16.h>
#include <cstdint>

#define NROWS 16384
#define DIM   512
#define NCODE 8192

#define LOSS_OFF   8388608
#define IDX_OFF    8388609
#define MD_OFF     8404993
#define COMMIT_OFF 8421377

// CTA tile 128(M) x 256(N), 8 warps (2M x 4N), warp tile 64x64, k-chunk 64
#define TM   128
#define TN   256
#define KC   64
#define NKC  (DIM / KC)            // 8
#define NNT  (NCODE / TN)          // 32
#define TOTAL_CHUNKS (NNT * NKC)   // 256

// dynamic smem: A resident 128K | B 2 stages x 32K | e2 1K
#define OFF_A    0
#define OFF_B    131072
#define BSTAGE   32768
#define OFF_E2   196608
#define SMEM_DYN 197632

__device__ float  g_e2[NCODE];
__device__ __half g_xh[NROWS * DIM];
__device__ __half g_ch[NCODE * DIM];
__device__ int    g_cand[NROWS * 8];

// ---------------------------------------------------------------------------
__device__ __forceinline__ uint32_t smem_u32(const void* p) {
    uint32_t a;
    asm("{ .reg .u64 t; cvta.to.shared.u64 t, %1; cvt.u32.u64 %0, t; }"
        : "=r"(a) : "l"(p));
    return a;
}
__device__ __forceinline__ void cpa16(uint32_t s, const void* g) {
    asm volatile("cp.async.cg.shared.global [%0], [%1], 16;" :: "r"(s), "l"(g));
}
__device__ __forceinline__ void ldsm4(uint32_t* r, uint32_t addr) {
    asm volatile("ldmatrix.sync.aligned.m8n8.x4.shared.b16 {%0,%1,%2,%3}, [%4];"
                 : "=r"(r[0]), "=r"(r[1]), "=r"(r[2]), "=r"(r[3]) : "r"(addr));
}
__device__ __forceinline__ void hmma(float* c, const uint32_t* a,
                                     uint32_t b0, uint32_t b1) {
    asm volatile(
        "mma.sync.aligned.m16n8k16.row.col.f32.f16.f16.f32 "
        "{%0,%1,%2,%3}, {%4,%5,%6,%7}, {%8,%9}, {%0,%1,%2,%3};"
        : "+f"(c[0]), "+f"(c[1]), "+f"(c[2]), "+f"(c[3])
        : "r"(a[0]), "r"(a[1]), "r"(a[2]), "r"(a[3]), "r"(b0), "r"(b1));
}

// ---------------------------------------------------------------------------
// Kernel 0: fp16 conversion of x and codebook
// ---------------------------------------------------------------------------
__global__ void split_kernel(const float* __restrict__ x,
                             const float* __restrict__ cb) {
    const int NX = NROWS * DIM / 4;
    const int NC = NCODE * DIM / 4;
    int i = blockIdx.x * blockDim.x + threadIdx.x;
    const float4* src;
    __half2* dh;
    int j;
    if (i < NX)           { src = (const float4*)x;  dh = (__half2*)g_xh; j = i; }
    else if (i < NX + NC) { src = (const float4*)cb; dh = (__half2*)g_ch; j = i - NX; }
    else return;
    float4 v = src[j];
    dh[j * 2 + 0] = __halves2half2(__float2half_rn(v.x), __float2half_rn(v.y));
    dh[j * 2 + 1] = __halves2half2(__float2half_rn(v.z), __float2half_rn(v.w));
}

// ---------------------------------------------------------------------------
// Kernel 1: codebook squared norms (one warp per row, fp32)
// ---------------------------------------------------------------------------
__global__ void sq_norms_kernel(const float* __restrict__ cb) {
    int warp = (blockIdx.x * blockDim.x + threadIdx.x) >> 5;
    int lane = threadIdx.x & 31;
    if (warp >= NCODE) return;
    const float4* base = (const float4*)(cb + (size_t)warp * DIM);
    float s = 0.f;
#pragma unroll
    for (int i = 0; i < 4; i++) {
        float4 v = base[lane + i * 32];
        s += v.x * v.x + v.y * v.y + v.z * v.z + v.w * v.w;
    }
#pragma unroll
    for (int o = 16; o > 0; o >>= 1) s += __shfl_down_sync(0xffffffffu, s, o);
    if (lane == 0) g_e2[warp] = s;
}

// ---------------------------------------------------------------------------
// Kernel 2: A-resident fp16 GEMM + running top-2-per-quarter candidates
// ---------------------------------------------------------------------------
__global__ __launch_bounds__(256, 1)
void vq_mma_kernel() {
    extern __shared__ __align__(1024) char smem[];
    const uint32_t sb = smem_u32(smem);
    float* e2s = (float*)(smem + OFF_E2);

    const int tid    = threadIdx.x;
    const int wid    = tid >> 5;
    const int lane   = tid & 31;
    const int warp_m = wid >> 2;   // 0..1
    const int warp_n = wid & 3;    // 0..3
    const int row0   = blockIdx.x * TM;

    const int rA  = (lane & 7) + ((lane >> 3) & 1) * 8;
    const int cA  = lane >> 4;
    const int rB  = (lane & 7) + (lane >> 4) * 8;
    const int cB  = (lane >> 3) & 1;
    const int swl = lane & 7;
    const uint32_t aRow = (uint32_t)(warp_m * 64 + rA) * 128;
    const uint32_t bRow = (uint32_t)(warp_n * 64 + rB) * 128;
    const int g  = lane >> 2;
    const int t4 = lane & 3;

    // ---- prologue: load resident A (128KB) as group 0 with B(0) ----
#pragma unroll
    for (int kc = 0; kc < 8; kc++) {
#pragma unroll
        for (int i = 0; i < 4; i++) {
            int id = tid + i * 256;
            int r = id >> 3, c = id & 7;
            uint32_t so = (uint32_t)(kc * 16384 + r * 128 + ((c ^ (r & 7)) << 4));
            cpa16(sb + OFF_A + so, g_xh + (size_t)(row0 + r) * DIM + kc * KC + c * 8);
        }
    }
    auto load_b = [&](int cc) {
        const int nt = cc >> 3;
        const int kc = cc & 7;
        const uint32_t st = sb + OFF_B + (uint32_t)(cc & 1) * BSTAGE;
#pragma unroll
        for (int i = 0; i < 8; i++) {
            int id = tid + i * 256;
            int r = id >> 3, c = id & 7;
            uint32_t so = (uint32_t)(r * 128 + ((c ^ (r & 7)) << 4));
            cpa16(st + so, g_ch + (size_t)(nt * TN + r) * DIM + kc * KC + c * 8);
        }
    };
    load_b(0); asm volatile("cp.async.commit_group;");
    load_b(1); asm volatile("cp.async.commit_group;");
    asm volatile("cp.async.wait_group 1;");
    __syncthreads();

    float acc[4][8][4];
#pragma unroll
    for (int a = 0; a < 4; a++)
#pragma unroll
        for (int b = 0; b < 8; b++)
#pragma unroll
            for (int c = 0; c < 4; c++) acc[a][b][c] = 0.f;

    // running top-2 per row-slot (slot = mi*2+p), replicated across t4 lanes
    float rv0[8], rv1[8];
    int   ri0[8], ri1[8];
#pragma unroll
    for (int s = 0; s < 8; s++) { rv0[s] = 3.4e38f; rv1[s] = 3.4e38f; ri0[s] = 0; ri1[s] = 0; }

#pragma unroll 1
    for (int cc = 0; cc < TOTAL_CHUNKS; cc++) {
        const int kc = cc & 7;
        if (kc == 0) e2s[tid] = g_e2[(cc >> 3) * TN + tid];

        const uint32_t stB = sb + OFF_B + (uint32_t)(cc & 1) * BSTAGE;
        const uint32_t stA = sb + OFF_A + (uint32_t)kc * 16384;
#pragma unroll
        for (int ks = 0; ks < 4; ks++) {
            uint32_t ah[4][4], bh[4][4];
            const uint32_t swA = (uint32_t)(((ks * 2 + cA) ^ swl) << 4);
            const uint32_t swB = (uint32_t)(((ks * 2 + cB) ^ swl) << 4);
#pragma unroll
            for (int mi = 0; mi < 4; mi++)
                ldsm4(ah[mi], stA + aRow + mi * 2048 + swA);
#pragma unroll
            for (int np = 0; np < 4; np++)
                ldsm4(bh[np], stB + bRow + np * 2048 + swB);
#pragma unroll
            for (int mi = 0; mi < 4; mi++)
#pragma unroll
                for (int nj = 0; nj < 8; nj++)
                    hmma(acc[mi][nj], ah[mi],
                         bh[nj >> 1][(nj & 1) * 2], bh[nj >> 1][(nj & 1) * 2 + 1]);
        }
        __syncthreads();
        if (cc + 2 < TOTAL_CHUNKS) load_b(cc + 2);
        asm volatile("cp.async.commit_group;");

        if (kc == 7) {
            // ---- epilogue: top-2 per warp_n quarter for this n-tile ----
            const int nt = cc >> 3;
#pragma unroll
            for (int mi = 0; mi < 4; mi++) {
#pragma unroll
                for (int p = 0; p < 2; p++) {
                    const int slot = mi * 2 + p;
                    float v0 = 3.4e38f, v1 = 3.4e38f;
                    int   i0 = 0, i1 = 0;
#pragma unroll
                    for (int nj = 0; nj < 8; nj++) {
#pragma unroll
                        for (int c = 0; c < 2; c++) {
                            int col = warp_n * 64 + nj * 8 + 2 * t4 + c;
                            float d = fmaf(-2.f, acc[mi][nj][p * 2 + c], e2s[col]);
                            int gi = nt * TN + col;
                            bool lt1 = d < v1;
                            bool lt0 = d < v0;
                            v1 = lt0 ? v0 : (lt1 ? d : v1);
                            i1 = lt0 ? i0 : (lt1 ? gi : i1);
                            v0 = lt0 ? d : v0;
                            i0 = lt0 ? gi : i0;
                            acc[mi][nj][p * 2 + c] = 0.f;
                        }
                    }
                    // merge sorted pairs across t4 lanes (xor 1, 2)
#pragma unroll
                    for (int off = 1; off <= 2; off <<= 1) {
                        float w0 = __shfl_xor_sync(0xffffffffu, v0, off);
                        int   j0 = __shfl_xor_sync(0xffffffffu, i0, off);
                        float w1 = __shfl_xor_sync(0xffffffffu, v1, off);
                        int   j1 = __shfl_xor_sync(0xffffffffu, i1, off);
                        bool a = w0 < v0;
                        float h0 = a ? w0 : v0;  int hi0 = a ? j0 : i0;
                        float l0 = a ? v0 : w0;  int li0 = a ? i0 : j0;
                        float s  = a ? w1 : v1;  int si  = a ? j1 : i1;
                        bool b = l0 < s;
                        v0 = h0; i0 = hi0;
                        v1 = b ? l0 : s; i1 = b ? li0 : si;
                    }
                    // merge into running top-2
                    {
                        bool a = v0 < rv0[slot];
                        float h0 = a ? v0 : rv0[slot]; int hi0 = a ? i0 : ri0[slot];
                        float l0 = a ? rv0[slot] : v0; int li0 = a ? ri0[slot] : i0;
                        float s  = a ? v1 : rv1[slot]; int si  = a ? i1 : ri1[slot];
                        bool b = l0 < s;
                        rv0[slot] = h0; ri0[slot] = hi0;
                        rv1[slot] = b ? l0 : s; ri1[slot] = b ? li0 : si;
                    }
                }
            }
        }
        asm volatile("cp.async.wait_group 1;");
        __syncthreads();
    }

    // ---- write 8 candidates per row (2 per warp_n quarter) ----
    if (t4 == 0) {
#pragma unroll
        for (int mi = 0; mi < 4; mi++)
#pragma unroll
            for (int p = 0; p < 2; p++) {
                const int slot = mi * 2 + p;
                int row = row0 + warp_m * 64 + mi * 16 + p * 8 + g;
                g_cand[row * 8 + warp_n * 2 + 0] = ri0[slot];
                g_cand[row * 8 + warp_n * 2 + 1] = ri1[slot];
            }
    }
}

// ---------------------------------------------------------------------------
// Kernel 3: exact fp32 refine of 8 candidates + gather + outputs
// ---------------------------------------------------------------------------
__global__ __launch_bounds__(256)
void vq_refine_kernel(const float* __restrict__ x,
                      const float* __restrict__ cb,
                      float* __restrict__ out) {
    __shared__ float sv[8];
    __shared__ int   si[8];
    __shared__ int   swin;

    const int row  = blockIdx.x;
    const int tid  = threadIdx.x;
    const int wid  = tid >> 5;
    const int lane = tid & 31;

    int cand = g_cand[row * 8 + wid];
    const float4* x4 = (const float4*)(x  + (size_t)row  * DIM);
    const float4* e4 = (const float4*)(cb + (size_t)cand * DIM);
    float s = 0.f;
#pragma unroll
    for (int i = 0; i < 4; i++) {
        float4 xv = x4[lane + i * 32];
        float4 ev = e4[lane + i * 32];
        float dx = xv.x - ev.x, dy = xv.y - ev.y;
        float dz = xv.z - ev.z, dw = xv.w - ev.w;
        s += dx * dx + dy * dy + dz * dz + dw * dw;
    }
#pragma unroll
    for (int o = 16; o > 0; o >>= 1) s += __shfl_down_sync(0xffffffffu, s, o);
    if (lane == 0) { sv[wid] = s; si[wid] = cand; }
    __syncthreads();

    if (tid == 0) {
        float bv = sv[0]; int bi = si[0];
#pragma unroll
        for (int k = 1; k < 8; k++) {
            float v = sv[k]; int ix = si[k];
            if (v < bv || (v == bv && ix < bi)) { bv = v; bi = ix; }
        }
        out[IDX_OFF + row] = (float)bi;
        out[MD_OFF + row]  = bv;
        swin = bi;
    }
    __syncthreads();

    if (tid < 128) {
        int win = swin;
        const float4* src = (const float4*)(cb + (size_t)win * DIM);
        float4*       dst = (float4*)(out + (size_t)row * DIM);
        dst[tid] = src[tid];
    }
}

// ---------------------------------------------------------------------------
// Kernel 4: deterministic loss reduction
// ---------------------------------------------------------------------------
__global__ void vq_loss_kernel(float* __restrict__ out) {
    __shared__ float s[256];
    int t = threadIdx.x;
    float acc = 0.f;
    for (int i = t; i < NROWS; i += 256) acc += out[MD_OFF + i];
    s[t] = acc;
    __syncthreads();
#pragma unroll
    for (int o = 128; o > 0; o >>= 1) {
        if (t < o) s[t] += s[t + o];
        __syncthreads();
    }
    if (t == 0) {
        out[COMMIT_OFF] = s[0];
        out[LOSS_OFF]   = 1.25f * s[0];
    }
}

// ---------------------------------------------------------------------------
extern "C" void kernel_launch(void* const* d_in, const int* in_sizes, int n_in,
                              void* d_out, int out_size) {
    const float* x  = (const float*)d_in[0];   // [16384, 512]
    const float* cb = (const float*)d_in[1];   // [8192, 512]
    float* out = (float*)d_out;

    cudaFuncSetAttribute(vq_mma_kernel,
                         cudaFuncAttributeMaxDynamicSharedMemorySize, SMEM_DYN);

    split_kernel<<<(NROWS + NCODE) * (DIM / 4) / 256, 256>>>(x, cb);
    sq_norms_kernel<<<NCODE / 8, 256>>>(cb);
    vq_mma_kernel<<<NROWS / TM, 256, SMEM_DYN>>>();
    vq_refine_kernel<<<NROWS, 256>>>(x, cb, out);
    vq_loss_kernel<<<1, 256>>>(out);
}

// round 6
// speedup vs baseline: 12.7704x; 1.0430x over previous
#include <cuda_runtime.h>
#include <cuda_fp16.h>
#include <cstdint>

#define NROWS 16384
#define DIM   512
#define NCODE 8192

#define LOSS_OFF   8388608
#define IDX_OFF    8388609
#define MD_OFF     8404993
#define COMMIT_OFF 8421377

// CTA tile 128(M) x 256(N), 8 warps (2M x 4N), warp tile 64x64, k-chunk 64
#define TM   128
#define TN   256
#define KC   64
#define NKC  (DIM / KC)            // 8
#define NNT  (NCODE / TN)          // 32
#define TOTAL_CHUNKS (NNT * NKC)   // 256

// dynamic smem: A resident 128K | B 2 stages x 32K | e2 1K | mbarriers
#define OFF_A    0
#define OFF_B    131072
#define BSTAGE   32768
#define OFF_E2   196608
#define OFF_MB   197632            // afull +0, full0 +8, full1 +16
#define SMEM_DYN 197696

#define A_BYTES  131072
#define B_CHUNK  32768

__device__ float  g_e2[NCODE];
// chunk-major, pre-swizzled packed operands:
// g_xh: [block(128 rows)][kc][row 0..127][128B swizzled row]
// g_ch: [nt(256 rows)*8 + kc][row 0..255][128B swizzled row]
__device__ __half g_xh[NROWS * DIM];
__device__ __half g_ch[NCODE * DIM];
__device__ int    g_cand[NROWS * 8];

// ---------------------------------------------------------------------------
__device__ __forceinline__ uint32_t smem_u32(const void* p) {
    uint32_t a;
    asm("{ .reg .u64 t; cvta.to.shared.u64 t, %1; cvt.u32.u64 %0, t; }"
        : "=r"(a) : "l"(p));
    return a;
}
__device__ __forceinline__ void ldsm4(uint32_t* r, uint32_t addr) {
    asm volatile("ldmatrix.sync.aligned.m8n8.x4.shared.b16 {%0,%1,%2,%3}, [%4];"
                 : "=r"(r[0]), "=r"(r[1]), "=r"(r[2]), "=r"(r[3]) : "r"(addr));
}
__device__ __forceinline__ void hmma(float* c, const uint32_t* a,
                                     uint32_t b0, uint32_t b1) {
    asm volatile(
        "mma.sync.aligned.m16n8k16.row.col.f32.f16.f16.f32 "
        "{%0,%1,%2,%3}, {%4,%5,%6,%7}, {%8,%9}, {%0,%1,%2,%3};"
        : "+f"(c[0]), "+f"(c[1]), "+f"(c[2]), "+f"(c[3])
        : "r"(a[0]), "r"(a[1]), "r"(a[2]), "r"(a[3]), "r"(b0), "r"(b1));
}
__device__ __forceinline__ void bulk_g2s(uint32_t dst, const void* src,
                                         uint32_t bytes, uint32_t mbar) {
    asm volatile(
        "cp.async.bulk.shared::cluster.global.mbarrier::complete_tx::bytes "
        "[%0], [%1], %2, [%3];"
        :: "r"(dst), "l"(src), "r"(bytes), "r"(mbar) : "memory");
}
#define MBAR_INIT(mb, c) asm volatile("mbarrier.init.shared.b64 [%0], %1;" :: "r"(mb), "r"(c) : "memory")
#define MBAR_EXPECT(mb, tx) asm volatile("mbarrier.arrive.expect_tx.shared.b64 _, [%0], %1;" :: "r"(mb), "r"(tx) : "memory")
#define MBAR_WAIT(mb, ph) do {                                              \
    uint32_t _m = (mb), _p = (ph), _d;                                      \
    asm volatile("{ .reg .pred p; mbarrier.try_wait.parity.acquire.cta.shared::cta.b64 p, [%1], %2; selp.b32 %0,1,0,p; }" \
                 : "=r"(_d) : "r"(_m), "r"(_p) : "memory");                 \
    if (!_d) {                                                              \
        asm volatile("{ .reg .pred P1;\nW%=:\n"                             \
            "mbarrier.try_wait.parity.acquire.cta.shared::cta.b64 P1, [%0], %1, 0x989680;\n" \
            "@P1 bra.uni D%=;\nbra.uni W%=;\nD%=:\n}"                       \
            :: "r"(_m), "r"(_p) : "memory");                                \
    }                                                                       \
} while (0)

// ---------------------------------------------------------------------------
// Kernel 0: fp16 convert + chunk-major pre-swizzled pack of x and codebook.
// One thread handles 8 consecutive elements (one 16B packed group).
// ---------------------------------------------------------------------------
__global__ void split_kernel(const float* __restrict__ x,
                             const float* __restrict__ cb) {
    const int NXG = NROWS * (DIM / 8);   // 1048576 groups
    const int NCG = NCODE * (DIM / 8);   // 524288 groups
    int i = blockIdx.x * blockDim.x + threadIdx.x;

    const float4* src;
    char* dstbase;
    int row, g;
    size_t tile_off;
    int rr;
    if (i < NXG) {
        src = (const float4*)x;
        dstbase = (char*)g_xh;
        row = i >> 6; g = i & 63;
        int b = row >> 7; rr = row & 127;
        int kc = g >> 3;
        tile_off = ((size_t)(b * 8 + kc) * 128 + rr) * 128;
    } else if (i < NXG + NCG) {
        int j = i - NXG;
        src = (const float4*)cb;
        dstbase = (char*)g_ch;
        row = j >> 6; g = j & 63;
        int nt = row >> 8; rr = row & 255;
        int kc = g >> 3;
        tile_off = ((size_t)(nt * 8 + kc) * 256 + rr) * 128;
    } else return;

    int gi = g & 7;
    // source: elements row*512 + g*8 .. +8  == float4 indices row*128 + g*2, +1
    float4 v0 = src[(size_t)row * 128 + g * 2];
    float4 v1 = src[(size_t)row * 128 + g * 2 + 1];
    __half2 h[4];
    h[0] = __halves2half2(__float2half_rn(v0.x), __float2half_rn(v0.y));
    h[1] = __halves2half2(__float2half_rn(v0.z), __float2half_rn(v0.w));
    h[2] = __halves2half2(__float2half_rn(v1.x), __float2half_rn(v1.y));
    h[3] = __halves2half2(__float2half_rn(v1.z), __float2half_rn(v1.w));
    uint32_t sw = (uint32_t)((gi ^ (rr & 7)) << 4);
    *(uint4*)(dstbase + tile_off + sw) = *(uint4*)h;
}

// ---------------------------------------------------------------------------
// Kernel 1: codebook squared norms (one warp per row, fp32)
// ---------------------------------------------------------------------------
__global__ void sq_norms_kernel(const float* __restrict__ cb) {
    int warp = (blockIdx.x * blockDim.x + threadIdx.x) >> 5;
    int lane = threadIdx.x & 31;
    if (warp >= NCODE) return;
    const float4* base = (const float4*)(cb + (size_t)warp * DIM);
    float s = 0.f;
#pragma unroll
    for (int i = 0; i < 4; i++) {
        float4 v = base[lane + i * 32];
        s += v.x * v.x + v.y * v.y + v.z * v.z + v.w * v.w;
    }
#pragma unroll
    for (int o = 16; o > 0; o >>= 1) s += __shfl_down_sync(0xffffffffu, s, o);
    if (lane == 0) g_e2[warp] = s;
}

// ---------------------------------------------------------------------------
// Kernel 2: A-resident fp16 GEMM (bulk-copy loads) + top-2-per-quarter
// ---------------------------------------------------------------------------
__global__ __launch_bounds__(256, 1)
void vq_mma_kernel() {
    extern __shared__ __align__(1024) char smem[];
    const uint32_t sb = smem_u32(smem);
    float* e2s = (float*)(smem + OFF_E2);
    const uint32_t mbA  = sb + OFF_MB;
    const uint32_t mbB0 = sb + OFF_MB + 8;

    const int tid    = threadIdx.x;
    const int lane   = tid & 31;
    const int wid    = tid >> 5;
    const int warp_m = wid >> 2;   // 0..1
    const int warp_n = wid & 3;    // 0..3
    const int blk    = blockIdx.x;
    const int row0   = blk * TM;

    const int rA  = (lane & 7) + ((lane >> 3) & 1) * 8;
    const int cA  = lane >> 4;
    const int rB  = (lane & 7) + (lane >> 4) * 8;
    const int cB  = (lane >> 3) & 1;
    const int swl = lane & 7;
    const uint32_t aRow = (uint32_t)(warp_m * 64 + rA) * 128;
    const uint32_t bRow = (uint32_t)(warp_n * 64 + rB) * 128;
    const int g  = lane >> 2;
    const int t4 = lane & 3;

    if (tid == 0) {
        MBAR_INIT(mbA, 1);
        MBAR_INIT(mbB0, 1);
        MBAR_INIT(mbB0 + 8, 1);
    }
    __syncthreads();

    if (tid == 0) {
        // A: 8 x 16KB bulks, one mbarrier (131072 bytes total)
        MBAR_EXPECT(mbA, A_BYTES);
        const char* asrc = (const char*)g_xh + (size_t)blk * A_BYTES;
#pragma unroll
        for (int kc = 0; kc < 8; kc++)
            bulk_g2s(sb + OFF_A + kc * 16384, asrc + kc * 16384, 16384, mbA);
        // B chunks 0, 1
        MBAR_EXPECT(mbB0, B_CHUNK);
        bulk_g2s(sb + OFF_B, (const char*)g_ch, B_CHUNK, mbB0);
        MBAR_EXPECT(mbB0 + 8, B_CHUNK);
        bulk_g2s(sb + OFF_B + BSTAGE, (const char*)g_ch + B_CHUNK, B_CHUNK, mbB0 + 8);
    }

    float acc[4][8][4];
#pragma unroll
    for (int a = 0; a < 4; a++)
#pragma unroll
        for (int b = 0; b < 8; b++)
#pragma unroll
            for (int c = 0; c < 4; c++) acc[a][b][c] = 0.f;

    float rv0[8], rv1[8];
    int   ri0[8], ri1[8];
#pragma unroll
    for (int s = 0; s < 8; s++) { rv0[s] = 3.4e38f; rv1[s] = 3.4e38f; ri0[s] = 0; ri1[s] = 0; }

    MBAR_WAIT(mbA, 0);

#pragma unroll 1
    for (int cc = 0; cc < TOTAL_CHUNKS; cc++) {
        const int kc = cc & 7;
        const int stg = cc & 1;
        if (kc == 0) e2s[tid] = g_e2[(cc >> 3) * TN + tid];

        MBAR_WAIT(mbB0 + stg * 8, (cc >> 1) & 1);

        const uint32_t stB = sb + OFF_B + (uint32_t)stg * BSTAGE;
        const uint32_t stA = sb + OFF_A + (uint32_t)kc * 16384;
#pragma unroll
        for (int ks = 0; ks < 4; ks++) {
            uint32_t ah[4][4], bh[4][4];
            const uint32_t swA = (uint32_t)(((ks * 2 + cA) ^ swl) << 4);
            const uint32_t swB = (uint32_t)(((ks * 2 + cB) ^ swl) << 4);
#pragma unroll
            for (int mi = 0; mi < 4; mi++)
                ldsm4(ah[mi], stA + aRow + mi * 2048 + swA);
#pragma unroll
            for (int np = 0; np < 4; np++)
                ldsm4(bh[np], stB + bRow + np * 2048 + swB);
#pragma unroll
            for (int mi = 0; mi < 4; mi++)
#pragma unroll
                for (int nj = 0; nj < 8; nj++)
                    hmma(acc[mi][nj], ah[mi],
                         bh[nj >> 1][(nj & 1) * 2], bh[nj >> 1][(nj & 1) * 2 + 1]);
        }

        if (kc == 7) {
            // ---- epilogue: top-2 per warp_n quarter for this n-tile ----
            const int nt = cc >> 3;
#pragma unroll
            for (int mi = 0; mi < 4; mi++) {
#pragma unroll
                for (int p = 0; p < 2; p++) {
                    const int slot = mi * 2 + p;
                    float v0 = 3.4e38f, v1 = 3.4e38f;
                    int   i0 = 0, i1 = 0;
#pragma unroll
                    for (int nj = 0; nj < 8; nj++) {
#pragma unroll
                        for (int c = 0; c < 2; c++) {
                            int col = warp_n * 64 + nj * 8 + 2 * t4 + c;
                            float d = fmaf(-2.f, acc[mi][nj][p * 2 + c], e2s[col]);
                            int gi = nt * TN + col;
                            bool lt1 = d < v1;
                            bool lt0 = d < v0;
                            v1 = lt0 ? v0 : (lt1 ? d : v1);
                            i1 = lt0 ? i0 : (lt1 ? gi : i1);
                            v0 = lt0 ? d : v0;
                            i0 = lt0 ? gi : i0;
                            acc[mi][nj][p * 2 + c] = 0.f;
                        }
                    }
#pragma unroll
                    for (int off = 1; off <= 2; off <<= 1) {
                        float w0 = __shfl_xor_sync(0xffffffffu, v0, off);
                        int   j0 = __shfl_xor_sync(0xffffffffu, i0, off);
                        float w1 = __shfl_xor_sync(0xffffffffu, v1, off);
                        int   j1 = __shfl_xor_sync(0xffffffffu, i1, off);
                        bool a = w0 < v0;
                        float h0 = a ? w0 : v0;  int hi0 = a ? j0 : i0;
                        float l0 = a ? v0 : w0;  int li0 = a ? i0 : j0;
                        float s  = a ? w1 : v1;  int si  = a ? j1 : i1;
                        bool b = l0 < s;
                        v0 = h0; i0 = hi0;
                        v1 = b ? l0 : s; i1 = b ? li0 : si;
                    }
                    {
                        bool a = v0 < rv0[slot];
                        float h0 = a ? v0 : rv0[slot]; int hi0 = a ? i0 : ri0[slot];
                        float l0 = a ? rv0[slot] : v0; int li0 = a ? ri0[slot] : i0;
                        float s  = a ? v1 : rv1[slot]; int si  = a ? i1 : ri1[slot];
                        bool b = l0 < s;
                        rv0[slot] = h0; ri0[slot] = hi0;
                        rv1[slot] = b ? l0 : s; ri1[slot] = b ? li0 : si;
                    }
                }
            }
        }

        __syncthreads();   // all warps done reading stage stg
        if (tid == 0 && cc + 2 < TOTAL_CHUNKS) {
            MBAR_EXPECT(mbB0 + stg * 8, B_CHUNK);
            bulk_g2s(sb + OFF_B + (uint32_t)stg * BSTAGE,
                     (const char*)g_ch + (size_t)(cc + 2) * B_CHUNK,
                     B_CHUNK, mbB0 + stg * 8);
        }
    }

    // ---- write 8 candidates per row (2 per warp_n quarter) ----
    if (t4 == 0) {
#pragma unroll
        for (int mi = 0; mi < 4; mi++)
#pragma unroll
            for (int p = 0; p < 2; p++) {
                const int slot = mi * 2 + p;
                int row = row0 + warp_m * 64 + mi * 16 + p * 8 + g;
                g_cand[row * 8 + warp_n * 2 + 0] = ri0[slot];
                g_cand[row * 8 + warp_n * 2 + 1] = ri1[slot];
            }
    }
}

// ---------------------------------------------------------------------------
// Kernel 3: exact fp32 refine of 8 candidates + gather + outputs
// ---------------------------------------------------------------------------
__global__ __launch_bounds__(256)
void vq_refine_kernel(const float* __restrict__ x,
                      const float* __restrict__ cb,
                      float* __restrict__ out) {
    __shared__ float sv[8];
    __shared__ int   si[8];
    __shared__ int   swin;

    const int row  = blockIdx.x;
    const int tid  = threadIdx.x;
    const int wid  = tid >> 5;
    const int lane = tid & 31;

    int cand = g_cand[row * 8 + wid];
    const float4* x4 = (const float4*)(x  + (size_t)row  * DIM);
    const float4* e4 = (const float4*)(cb + (size_t)cand * DIM);
    float s = 0.f;
#pragma unroll
    for (int i = 0; i < 4; i++) {
        float4 xv = x4[lane + i * 32];
        float4 ev = e4[lane + i * 32];
        float dx = xv.x - ev.x, dy = xv.y - ev.y;
        float dz = xv.z - ev.z, dw = xv.w - ev.w;
        s += dx * dx + dy * dy + dz * dz + dw * dw;
    }
#pragma unroll
    for (int o = 16; o > 0; o >>= 1) s += __shfl_down_sync(0xffffffffu, s, o);
    if (lane == 0) { sv[wid] = s; si[wid] = cand; }
    __syncthreads();

    if (tid == 0) {
        float bv = sv[0]; int bi = si[0];
#pragma unroll
        for (int k = 1; k < 8; k++) {
            float v = sv[k]; int ix = si[k];
            if (v < bv || (v == bv && ix < bi)) { bv = v; bi = ix; }
        }
        out[IDX_OFF + row] = (float)bi;
        out[MD_OFF + row]  = bv;
        swin = bi;
    }
    __syncthreads();

    if (tid < 128) {
        int win = swin;
        const float4* src = (const float4*)(cb + (size_t)win * DIM);
        float4*       dst = (float4*)(out + (size_t)row * DIM);
        dst[tid] = src[tid];
    }
}

// ---------------------------------------------------------------------------
// Kernel 4: deterministic loss reduction
// ---------------------------------------------------------------------------
__global__ void vq_loss_kernel(float* __restrict__ out) {
    __shared__ float s[512];
    int t = threadIdx.x;
    float acc = 0.f;
    for (int i = t; i < NROWS; i += 512) acc += out[MD_OFF + i];
    s[t] = acc;
    __syncthreads();
#pragma unroll
    for (int o = 256; o > 0; o >>= 1) {
        if (t < o) s[t] += s[t + o];
        __syncthreads();
    }
    if (t == 0) {
        out[COMMIT_OFF] = s[0];
        out[LOSS_OFF]   = 1.25f * s[0];
    }
}

// ---------------------------------------------------------------------------
extern "C" void kernel_launch(void* const* d_in, const int* in_sizes, int n_in,
                              void* d_out, int out_size) {
    const float* x  = (const float*)d_in[0];   // [16384, 512]
    const float* cb = (const float*)d_in[1];   // [8192, 512]
    float* out = (float*)d_out;

    cudaFuncSetAttribute(vq_mma_kernel,
                         cudaFuncAttributeMaxDynamicSharedMemorySize, SMEM_DYN);

    split_kernel<<<(NROWS + NCODE) * (DIM / 8) / 256, 256>>>(x, cb);
    sq_norms_kernel<<<NCODE / 8, 256>>>(cb);
    vq_mma_kernel<<<NROWS / TM, 256, SMEM_DYN>>>();
    vq_refine_kernel<<<NROWS, 256>>>(x, cb, out);
    vq_loss_kernel<<<1, 512>>>(out);
}